// round 2
// baseline (speedup 1.0000x reference)
#include <cuda_runtime.h>
#include <cuda_bf16.h>

// Multilevel DB4 DWT, fused across all 11 levels.
// One CTA per row: load 16KB row -> smem, 11 in-place levels
// (register-staged, 2 barriers/level), store once.
// DRAM traffic = 1 read + 1 write of the 64MB matrix = 128MB total.
//
// Boundary semantics (matches reference's W[:L,:L] slicing):
//   lev 0  : periodic wrap (last pair reads x[0], x[1])
//   lev >=1: truncated (taps beyond L are zero)

#define DWT_N       4096
#define DWT_THREADS 256
#define DWT_NLEV    11          // log2(4096) - 1
#define MAX_PAIRS   ((DWT_N / 2) / DWT_THREADS)   // 8 pairs/thread at level 0

__global__ __launch_bounds__(DWT_THREADS)
void dwt_db4_fused_kernel(const float* __restrict__ in,
                          float* __restrict__ out)
{
    __shared__ float s[DWT_N];   // 16 KB

    const int row = blockIdx.x;
    const float* src = in  + (size_t)row * DWT_N;
    float*       dst = out + (size_t)row * DWT_N;

    // ---- coalesced vectorized load of the full row ----
    {
        const float4* src4 = reinterpret_cast<const float4*>(src);
        float4*       s4   = reinterpret_cast<float4*>(s);
        #pragma unroll
        for (int i = threadIdx.x; i < DWT_N / 4; i += DWT_THREADS)
            s4[i] = src4[i];
    }
    __syncthreads();

    const float c0 =  0.4829629131445341f;
    const float c1 =  0.8365163037378079f;
    const float c2 =  0.2241438680420134f;
    const float c3 = -0.1294095225512604f;

    #pragma unroll 1
    for (int lev = 0; lev < DWT_NLEV; ++lev) {
        const int L = DWT_N >> lev;
        const int H = L >> 1;

        float ra[MAX_PAIRS];
        float rd[MAX_PAIRS];

        // Phase 1: read x, compute pairs into registers.
        int cnt = 0;
        for (int k = threadIdx.x; k < H; k += DWT_THREADS) {
            const int i0 = 2 * k;
            const float2 xa = *reinterpret_cast<const float2*>(&s[i0]);

            float2 xb;
            const int i2 = i0 + 2;
            if (i2 < L) {
                xb = *reinterpret_cast<const float2*>(&s[i2]);
            } else if (lev == 0) {
                // full-size matrix: periodic wrap
                xb = *reinterpret_cast<const float2*>(&s[0]);
            } else {
                // sliced matrix W[:L,:L]: taps beyond L are zero
                xb = make_float2(0.0f, 0.0f);
            }

            ra[cnt] = c0 * xa.x + c1 * xa.y + c2 * xb.x + c3 * xb.y;
            rd[cnt] = c3 * xa.x - c2 * xa.y + c1 * xb.x - c0 * xb.y;
            ++cnt;
        }
        __syncthreads();

        // Phase 2: write back in place (a -> [0,H), d -> [H,L)).
        cnt = 0;
        for (int k = threadIdx.x; k < H; k += DWT_THREADS) {
            s[k]     = ra[cnt];
            s[H + k] = rd[cnt];
            ++cnt;
        }
        __syncthreads();
    }

    // ---- coalesced vectorized store ----
    {
        const float4* s4   = reinterpret_cast<const float4*>(s);
        float4*       dst4 = reinterpret_cast<float4*>(dst);
        #pragma unroll
        for (int i = threadIdx.x; i < DWT_N / 4; i += DWT_THREADS)
            dst4[i] = s4[i];
    }
}

extern "C" void kernel_launch(void* const* d_in, const int* in_sizes, int n_in,
                              void* d_out, int out_size)
{
    const float* x = (const float*)d_in[0];   // [B, N] float32
    // d_in[1] = W, [N, N] float32 — structure known analytically; unused.
    float* out = (float*)d_out;

    const int total = in_sizes[0];
    const int B = total / DWT_N;              // 4096 rows

    dwt_db4_fused_kernel<<<B, DWT_THREADS>>>(x, out);
}

// round 3
// speedup vs baseline: 1.7461x; 1.7461x over previous
#include <cuda_runtime.h>
#include <cuda_bf16.h>

// Multilevel DB4 DWT (11 levels), register-resident cascade.
//
// Thread t owns x[16t..16t+16). Its a-outputs at each level are again a
// contiguous chunk -> levels 0-3 run in registers with only a 2-float
// neighbor exchange per level. d-outputs are final -> stored to global
// immediately. Levels 4-10 (256 values) finish in one warp via smem.
//
// Boundary (matches reference W[:L,:L] slicing):
//   level 0 : periodic wrap (last pair reads x[0], x[1])
//   level>=1: truncated (taps beyond L are zero)

#define DWT_N 4096
#define NTH   256

__device__ __forceinline__ void dwt_pair(float x0, float x1, float x2, float x3,
                                         float& a, float& d)
{
    const float c0 =  0.4829629131445341f;
    const float c1 =  0.8365163037378079f;
    const float c2 =  0.2241438680420134f;
    const float c3 = -0.1294095225512604f;
    a = c0 * x0 + c1 * x1 + c2 * x2 + c3 * x3;
    d = c3 * x0 - c2 * x1 + c1 * x2 - c0 * x3;
}

__global__ __launch_bounds__(NTH)
void dwt_db4_reg_kernel(const float* __restrict__ in,
                        float* __restrict__ out)
{
    __shared__ float exA[2 * NTH];   // neighbor-exchange ping
    __shared__ float exB[2 * NTH];   // neighbor-exchange pong
    __shared__ float sm[NTH];        // tail signal (levels 4-10)

    const int t = threadIdx.x;
    const float* src = in  + (size_t)blockIdx.x * DWT_N;
    float*       dst = out + (size_t)blockIdx.x * DWT_N;

    // ---- load chunk x[16t .. 16t+16) : 4x LDG.128 ----
    float v[16];
    {
        const float4* s4 = reinterpret_cast<const float4*>(src) + 4 * t;
        #pragma unroll
        for (int j = 0; j < 4; ++j) {
            float4 f = s4[j];
            v[4*j+0] = f.x; v[4*j+1] = f.y; v[4*j+2] = f.z; v[4*j+3] = f.w;
        }
    }

    // ================= level 0 (L=4096): periodic wrap =================
    *reinterpret_cast<float2*>(&exA[2 * t]) = make_float2(v[0], v[1]);
    __syncthreads();
    float2 nb = *reinterpret_cast<const float2*>(&exA[2 * ((t + 1) & (NTH - 1))]);

    float a0[8], d0[8];
    #pragma unroll
    for (int k = 0; k < 8; ++k) {
        float x2 = (2*k + 2 < 16) ? v[2*k + 2] : nb.x;
        float x3 = (2*k + 3 < 16) ? v[2*k + 3] : nb.y;
        dwt_pair(v[2*k], v[2*k + 1], x2, x3, a0[k], d0[k]);
    }
    {   // d0 -> out[2048 + 8t ..), final
        float4* o4 = reinterpret_cast<float4*>(dst + 2048 + 8 * t);
        o4[0] = make_float4(d0[0], d0[1], d0[2], d0[3]);
        o4[1] = make_float4(d0[4], d0[5], d0[6], d0[7]);
    }

    // ================= level 1 (L=2048): truncated =================
    *reinterpret_cast<float2*>(&exB[2 * t]) = make_float2(a0[0], a0[1]);
    __syncthreads();
    nb = (t == NTH - 1) ? make_float2(0.f, 0.f)
                        : *reinterpret_cast<const float2*>(&exB[2 * (t + 1)]);

    float a1[4], d1[4];
    #pragma unroll
    for (int k = 0; k < 4; ++k) {
        float x2 = (2*k + 2 < 8) ? a0[2*k + 2] : nb.x;
        float x3 = (2*k + 3 < 8) ? a0[2*k + 3] : nb.y;
        dwt_pair(a0[2*k], a0[2*k + 1], x2, x3, a1[k], d1[k]);
    }
    *reinterpret_cast<float4*>(dst + 1024 + 4 * t) =
        make_float4(d1[0], d1[1], d1[2], d1[3]);

    // ================= level 2 (L=1024): truncated =================
    *reinterpret_cast<float2*>(&exA[2 * t]) = make_float2(a1[0], a1[1]);
    __syncthreads();
    nb = (t == NTH - 1) ? make_float2(0.f, 0.f)
                        : *reinterpret_cast<const float2*>(&exA[2 * (t + 1)]);

    float a2[2], d2[2];
    #pragma unroll
    for (int k = 0; k < 2; ++k) {
        float x2 = (2*k + 2 < 4) ? a1[2*k + 2] : nb.x;
        float x3 = (2*k + 3 < 4) ? a1[2*k + 3] : nb.y;
        dwt_pair(a1[2*k], a1[2*k + 1], x2, x3, a2[k], d2[k]);
    }
    *reinterpret_cast<float2*>(dst + 512 + 2 * t) = make_float2(d2[0], d2[1]);

    // ================= level 3 (L=512): truncated =================
    *reinterpret_cast<float2*>(&exB[2 * t]) = make_float2(a2[0], a2[1]);
    __syncthreads();
    nb = (t == NTH - 1) ? make_float2(0.f, 0.f)
                        : *reinterpret_cast<const float2*>(&exB[2 * (t + 1)]);

    float a3, d3;
    dwt_pair(a2[0], a2[1], nb.x, nb.y, a3, d3);
    dst[256 + t] = d3;

    // ---- hand the 256 remaining a-values to warp 0 ----
    sm[t] = a3;
    __syncthreads();

    if (t < 32) {
        // levels 4-10 on sm[0:256), in place, warp-synchronous
        #pragma unroll
        for (int l = 0; l < 7; ++l) {
            const int L = 256 >> l;
            const int H = L >> 1;
            float ra[4], rd[4];
            int cnt = 0;
            #pragma unroll
            for (int k = t; k < H; k += 32) {
                float x0 = sm[2*k],     x1 = sm[2*k + 1];
                float x2 = (2*k + 2 < L) ? sm[2*k + 2] : 0.f;
                float x3 = (2*k + 3 < L) ? sm[2*k + 3] : 0.f;
                dwt_pair(x0, x1, x2, x3, ra[cnt], rd[cnt]);
                ++cnt;
            }
            __syncwarp();
            cnt = 0;
            #pragma unroll
            for (int k = t; k < H; k += 32) {
                sm[k]     = ra[cnt];
                sm[H + k] = rd[cnt];
                ++cnt;
            }
            __syncwarp();
        }
        // out[0:256) final
        #pragma unroll
        for (int i = t; i < 64; i += 32)
            reinterpret_cast<float4*>(dst)[i] =
                reinterpret_cast<const float4*>(sm)[i];
    }
}

extern "C" void kernel_launch(void* const* d_in, const int* in_sizes, int n_in,
                              void* d_out, int out_size)
{
    const float* x = (const float*)d_in[0];   // [B, N] float32
    // d_in[1] = W : structure known analytically; unused.
    float* out = (float*)d_out;

    const int B = in_sizes[0] / DWT_N;        // 4096 rows
    dwt_db4_reg_kernel<<<B, NTH>>>(x, out);
}